// round 1
// baseline (speedup 1.0000x reference)
#include <cuda_runtime.h>
#include <cuda_bf16.h>
#include <math.h>

// Problem constants (fixed by setup_inputs)
#define HDIM 1024
#define KDIM 2048      // 2*H
#define GATES 5
#define BSZ 32
#define STEPS 128
#define AMB 32
#define STARTI 256
#define CHART_LEN 384
#define NROWS (STEPS * BSZ * AMB)   // 131072

// GEMM tiling
#define BM 64
#define BN 32
#define BK 32
#define APAD 4     // As row pad
#define UPAD 8     // Us row pad (keeps float2 alignment, spreads STS banks)

// Scratch for c and h per (step,batch,amb) row: 512 MB each (static device mem,
// allowed; no runtime allocation).
__device__ float g_c[(size_t)NROWS * HDIM];
__device__ float g_h[(size_t)NROWS * HDIM];

__device__ __forceinline__ float sigmoidf_(float x) {
    return 1.0f / (1.0f + __expf(-x));
}

// ---------------------------------------------------------------------------
// K1: copy chart rows [0, 256) into out (rows [256,384) are fully written by K3)
// ---------------------------------------------------------------------------
__global__ __launch_bounds__(256) void copy_kernel(const float4* __restrict__ src,
                                                   float4* __restrict__ dst) {
    int i4 = blockIdx.x * 256 + threadIdx.x;          // over 32*256*2048/4 float4
    const int per_batch = STARTI * KDIM / 4;          // 131072
    const int full_batch = CHART_LEN * KDIM / 4;      // 196608
    int b = i4 / per_batch;
    int rem = i4 - b * per_batch;
    size_t s = (size_t)b * full_batch + rem;
    dst[s] = src[s];
}

// ---------------------------------------------------------------------------
// K2: fused gather + GEMM + LSTM gate epilogue.
// Row r = ((step*32 + b)*32 + a). ops index for row r is simply 2r.
// hh[k] = k < 1024 ? chart[b, opsL, 1024+k] : chart[b, opsR, k]
// preact[r][q*1024+j] = sum_k hh[r][k] * U[q*1024+j][k] + bias[q*1024+j]
// c = fL*ccL + fR*ccR + i*u ;  h = o*tanh(c)
// ---------------------------------------------------------------------------
__global__ __launch_bounds__(256) void gemm_gates_kernel(
    const float* __restrict__ chart, const int* __restrict__ ops,
    const float* __restrict__ U, const float* __restrict__ bias)
{
    __shared__ __align__(16) float As[BK][BM + APAD];            // [k][row]
    __shared__ __align__(16) float Us[BK][GATES * BN + UPAD];    // [k][g*32+j]
    __shared__ const float* rowPtr[BM][2];                       // cc/hh base ptrs

    const int tid = threadIdx.x;
    const int tx = tid & 15;       // j pairs
    const int ty = tid >> 4;       // row quads
    const int jcol0 = blockIdx.x * BN;
    const size_t rbase = (size_t)blockIdx.y * BM;

    // Per-row child pointers (chart base + (b*CHART_LEN + op)*2048)
    if (tid < 2 * BM) {
        int i = tid >> 1, side = tid & 1;
        size_t r = rbase + i;
        int bb = ((int)r >> 5) & 31;
        int op = ops[2 * r + side];
        rowPtr[i][side] = chart + ((size_t)bb * CHART_LEN + op) * KDIM;
    }
    __syncthreads();

    float acc[GATES][4][2];
#pragma unroll
    for (int g = 0; g < GATES; g++)
#pragma unroll
        for (int i = 0; i < 4; i++) { acc[g][i][0] = 0.f; acc[g][i][1] = 0.f; }

    for (int kc = 0; kc < KDIM / BK; kc++) {
        const int kbase = kc * BK;
        // ---- load A tile (gathered) : 64 rows x 32 k = 512 float4 ----
#pragma unroll
        for (int i2 = 0; i2 < 2; i2++) {
            int id = tid + i2 * 256;
            int row = id >> 3, kq = id & 7;
            int k = kbase + kq * 4;
            const float* src = (k < HDIM) ? (rowPtr[row][0] + HDIM + k)
                                          : (rowPtr[row][1] + k);
            float4 v = *(const float4*)src;
            As[kq * 4 + 0][row] = v.x;
            As[kq * 4 + 1][row] = v.y;
            As[kq * 4 + 2][row] = v.z;
            As[kq * 4 + 3][row] = v.w;
        }
        // ---- load U tile : 5 gates x 32 j x 32 k = 1280 float4 ----
#pragma unroll
        for (int t = 0; t < 5; t++) {
            int f = tid + t * 256;
            int g = f >> 8;
            int rem = f & 255;
            int jj = rem >> 3, kq = rem & 7;
            const float4 v = *(const float4*)(U + (size_t)(g * HDIM + jcol0 + jj) * KDIM
                                              + kbase + kq * 4);
            Us[kq * 4 + 0][g * BN + jj] = v.x;
            Us[kq * 4 + 1][g * BN + jj] = v.y;
            Us[kq * 4 + 2][g * BN + jj] = v.z;
            Us[kq * 4 + 3][g * BN + jj] = v.w;
        }
        __syncthreads();
        // ---- FMA ----
#pragma unroll
        for (int kk = 0; kk < BK; kk++) {
            float4 a4 = *(const float4*)&As[kk][ty * 4];
            float a[4] = {a4.x, a4.y, a4.z, a4.w};
            float2 uf[GATES];
#pragma unroll
            for (int g = 0; g < GATES; g++)
                uf[g] = *(const float2*)&Us[kk][g * BN + tx * 2];
#pragma unroll
            for (int g = 0; g < GATES; g++)
#pragma unroll
                for (int i = 0; i < 4; i++) {
                    acc[g][i][0] += a[i] * uf[g].x;
                    acc[g][i][1] += a[i] * uf[g].y;
                }
        }
        __syncthreads();
    }

    // ---- epilogue: gates -> c,h ----
#pragma unroll
    for (int i = 0; i < 4; i++) {
        int rl = ty * 4 + i;
        size_t r = rbase + rl;
        const float* pL = rowPtr[rl][0];
        const float* pR = rowPtr[rl][1];
#pragma unroll
        for (int jj = 0; jj < 2; jj++) {
            int j = jcol0 + tx * 2 + jj;
            float pi  = acc[0][i][jj] + bias[j];
            float pfl = acc[1][i][jj] + bias[HDIM + j];
            float pfr = acc[2][i][jj] + bias[2 * HDIM + j];
            float po  = acc[3][i][jj] + bias[3 * HDIM + j];
            float pu  = acc[4][i][jj] + bias[4 * HDIM + j];
            float ig = sigmoidf_(pi);
            float fl = sigmoidf_(pfl);
            float fr = sigmoidf_(pfr);
            float og = sigmoidf_(po);
            float ut = tanhf(pu);
            float c = fl * pL[j] + fr * pR[j] + ig * ut;
            float h = og * tanhf(c);
            g_c[r * HDIM + j] = c;
            g_h[r * HDIM + j] = h;
        }
    }
}

// ---------------------------------------------------------------------------
// K3: per (step, batch): energy, softmax over amb, weighted combine, write row.
// ---------------------------------------------------------------------------
__global__ __launch_bounds__(256) void combine_kernel(const float* __restrict__ eu,
                                                      float* __restrict__ out)
{
    __shared__ float s_eu[HDIM];
    __shared__ float s_e[AMB];
    __shared__ float s_w[AMB];
    __shared__ float s_red[8];
    __shared__ float s_unorm;

    const int tid = threadIdx.x;
    const int sb = blockIdx.x;            // step*32 + b
    const int step = sb >> 5;
    const int bb = sb & 31;
    const size_t base = (size_t)sb * AMB * HDIM;

    // load energy_u into smem + ||eu||^2
    float part = 0.f;
#pragma unroll
    for (int t = 0; t < 4; t++) {
        int j = tid + t * 256;
        float v = eu[j];
        s_eu[j] = v;
        part += v * v;
    }
#pragma unroll
    for (int off = 16; off; off >>= 1) part += __shfl_xor_sync(0xffffffffu, part, off);
    if ((tid & 31) == 0) s_red[tid >> 5] = part;
    __syncthreads();
    if (tid == 0) {
        float s = 0.f;
#pragma unroll
        for (int w = 0; w < 8; w++) s += s_red[w];
        s_unorm = fmaxf(sqrtf(s), 1e-8f);
    }
    __syncthreads();

    // per-amb energy: e[a] = (h.eu) / (u_norm * max(||h||, eps))
    const int warp = tid >> 5, lane = tid & 31;
#pragma unroll
    for (int t = 0; t < 4; t++) {
        int a = warp * 4 + t;
        const float* hrow = g_h + base + (size_t)a * HDIM;
        float s2 = 0.f, se = 0.f;
        for (int j = lane; j < HDIM; j += 32) {
            float hv = hrow[j];
            s2 += hv * hv;
            se += hv * s_eu[j];
        }
#pragma unroll
        for (int off = 16; off; off >>= 1) {
            s2 += __shfl_xor_sync(0xffffffffu, s2, off);
            se += __shfl_xor_sync(0xffffffffu, se, off);
        }
        if (lane == 0) {
            float hn = fmaxf(sqrtf(s2), 1e-8f);
            s_e[a] = se / (s_unorm * hn);
        }
    }
    __syncthreads();

    // softmax over amb (temperature = 1)
    if (tid < 32) {
        float x = s_e[tid];
        float m = x;
#pragma unroll
        for (int off = 16; off; off >>= 1) m = fmaxf(m, __shfl_xor_sync(0xffffffffu, m, off));
        float p = __expf(x - m);
        float s = p;
#pragma unroll
        for (int off = 16; off; off >>= 1) s += __shfl_xor_sync(0xffffffffu, s, off);
        s_w[tid] = p / s;
    }
    __syncthreads();

    // combined = [sum_a s*c, sum_a s*h] -> out row (b, 256+step)
    float* orow = out + ((size_t)bb * CHART_LEN + (STARTI + step)) * KDIM;
#pragma unroll
    for (int t = 0; t < 4; t++) {
        int j = tid + t * 256;
        float accC = 0.f, accH = 0.f;
#pragma unroll 8
        for (int a = 0; a < AMB; a++) {
            float w = s_w[a];
            accC += w * g_c[base + (size_t)a * HDIM + j];
            accH += w * g_h[base + (size_t)a * HDIM + j];
        }
        orow[j] = accC;
        orow[HDIM + j] = accH;
    }
}

// ---------------------------------------------------------------------------
extern "C" void kernel_launch(void* const* d_in, const int* in_sizes, int n_in,
                              void* d_out, int out_size) {
    const float* chart = (const float*)d_in[0];
    const int*   ops   = (const int*)d_in[1];
    // d_in[2] = start_index (fixed 256, compile-time)
    const float* U     = (const float*)d_in[3];
    const float* bias  = (const float*)d_in[4];
    const float* eu    = (const float*)d_in[5];
    float* out = (float*)d_out;

    // K1: copy untouched chart region (rows [0,256) per batch)
    const int n4 = BSZ * STARTI * KDIM / 4;     // 4,194,304 float4
    copy_kernel<<<n4 / 256, 256>>>((const float4*)chart, (float4*)out);

    // K2: all 128 steps at once (ops indices are < START, so steps are independent)
    dim3 g2(HDIM / BN, NROWS / BM);             // (32, 2048)
    gemm_gates_kernel<<<g2, 256>>>(chart, ops, U, bias);

    // K3: softmax + combine + write rows [256,384)
    combine_kernel<<<STEPS * BSZ, 256>>>(eu, out);
}

// round 2
// speedup vs baseline: 12.4054x; 12.4054x over previous
#include <cuda_runtime.h>
#include <cuda_bf16.h>
#include <math.h>

// Problem constants (fixed by setup_inputs)
#define HDIM 1024
#define KDIM 2048      // 2*H
#define GATES 5
#define BSZ 32
#define STEPS 128
#define AMB 32
#define STARTI 256
#define CHART_LEN 384
#define NROWS (STEPS * BSZ * AMB)   // 131072
#define NX (BSZ * STARTI)           // 8192 distinct (b,op) h-vectors
#define PPW (2 * GATES * HDIM)      // 10240 cols of PP per x-row

// GEMM tiling (same proven 98%-FFMA-roofline structure as round 1)
#define BM 64
#define BN 32
#define BK 32
#define APAD 4
#define UPAD 8

// Static device scratch (no runtime allocation allowed)
__device__ float g_p[(size_t)NX * PPW];        // 336 MB: PP[x, side*5120 + g*1024 + j]
__device__ float g_c[(size_t)NROWS * HDIM];    // 512 MB
__device__ float g_h[(size_t)NROWS * HDIM];    // 512 MB

__device__ __forceinline__ float sigmoidf_(float x) {
    return 1.0f / (1.0f + __expf(-x));
}

// ---------------------------------------------------------------------------
// K1: copy chart rows [0, 256) into out (rows [256,384) fully written by K4)
// ---------------------------------------------------------------------------
__global__ __launch_bounds__(256) void copy_kernel(const float4* __restrict__ src,
                                                   float4* __restrict__ dst) {
    int i4 = blockIdx.x * 256 + threadIdx.x;
    const int per_batch = STARTI * KDIM / 4;
    const int full_batch = CHART_LEN * KDIM / 4;
    int b = i4 / per_batch;
    int rem = i4 - b * per_batch;
    size_t s = (size_t)b * full_batch + rem;
    dst[s] = src[s];
}

// ---------------------------------------------------------------------------
// K2: PP[x, side*5120 + g*1024 + j] = sum_k chart[b,op,1024+k] * U[g*1024+j, side*1024+k]
//     x = b*256 + op   (one GEMM over the 8192 DISTINCT h-vectors, 0.172 TFLOP)
// ---------------------------------------------------------------------------
__global__ __launch_bounds__(256) void pp_gemm_kernel(
    const float* __restrict__ chart, const float* __restrict__ U)
{
    __shared__ __align__(16) float As[BK][BM + APAD];            // [k][row]
    __shared__ __align__(16) float Us[BK][GATES * BN + UPAD];    // [k][g*32+j]
    __shared__ const float* rowPtr[BM];

    const int tid = threadIdx.x;
    const int tx = tid & 15;
    const int ty = tid >> 4;
    const int jcol0 = blockIdx.x * BN;
    const int xbase = blockIdx.y * BM;
    const int side = blockIdx.z;
    const int uofs = side * HDIM;

    if (tid < BM) {
        int x = xbase + tid;
        int bb = x >> 8, op = x & 255;
        rowPtr[tid] = chart + ((size_t)(bb * CHART_LEN + op)) * KDIM + HDIM;
    }
    __syncthreads();

    float acc[GATES][4][2];
#pragma unroll
    for (int g = 0; g < GATES; g++)
#pragma unroll
        for (int i = 0; i < 4; i++) { acc[g][i][0] = 0.f; acc[g][i][1] = 0.f; }

    for (int kc = 0; kc < HDIM / BK; kc++) {
        const int kbase = kc * BK;
        // A tile: 64 rows x 32 k = 512 float4
#pragma unroll
        for (int i2 = 0; i2 < 2; i2++) {
            int id = tid + i2 * 256;
            int row = id >> 3, kq = id & 7;
            float4 v = *(const float4*)(rowPtr[row] + kbase + kq * 4);
            As[kq * 4 + 0][row] = v.x;
            As[kq * 4 + 1][row] = v.y;
            As[kq * 4 + 2][row] = v.z;
            As[kq * 4 + 3][row] = v.w;
        }
        // U tile: 5 gates x 32 j x 32 k = 1280 float4
#pragma unroll
        for (int t = 0; t < 5; t++) {
            int f = tid + t * 256;
            int g = f >> 8;
            int rem = f & 255;
            int jj = rem >> 3, kq = rem & 7;
            const float4 v = *(const float4*)(U + (size_t)(g * HDIM + jcol0 + jj) * KDIM
                                              + uofs + kbase + kq * 4);
            Us[kq * 4 + 0][g * BN + jj] = v.x;
            Us[kq * 4 + 1][g * BN + jj] = v.y;
            Us[kq * 4 + 2][g * BN + jj] = v.z;
            Us[kq * 4 + 3][g * BN + jj] = v.w;
        }
        __syncthreads();
#pragma unroll
        for (int kk = 0; kk < BK; kk++) {
            float4 a4 = *(const float4*)&As[kk][ty * 4];
            float a[4] = {a4.x, a4.y, a4.z, a4.w};
            float2 uf[GATES];
#pragma unroll
            for (int g = 0; g < GATES; g++)
                uf[g] = *(const float2*)&Us[kk][g * BN + tx * 2];
#pragma unroll
            for (int g = 0; g < GATES; g++)
#pragma unroll
                for (int i = 0; i < 4; i++) {
                    acc[g][i][0] += a[i] * uf[g].x;
                    acc[g][i][1] += a[i] * uf[g].y;
                }
        }
        __syncthreads();
    }

    // store PP
#pragma unroll
    for (int i = 0; i < 4; i++) {
        size_t x = (size_t)xbase + ty * 4 + i;
        float* dst = g_p + x * PPW + side * (GATES * HDIM);
#pragma unroll
        for (int g = 0; g < GATES; g++) {
            int j = g * HDIM + jcol0 + tx * 2;
            dst[j] = acc[g][i][0];
            dst[j + 1] = acc[g][i][1];
        }
    }
}

// ---------------------------------------------------------------------------
// K3: per row r: preact = PP[xL, left] + PP[xR, right] + bias -> gates -> c,h
// ---------------------------------------------------------------------------
__global__ __launch_bounds__(256) void gates_kernel(
    const float* __restrict__ chart, const int* __restrict__ ops,
    const float* __restrict__ bias)
{
    const size_t r = blockIdx.x;
    const int bb = ((int)r >> 5) & 31;
    const int opL = ops[2 * r];
    const int opR = ops[2 * r + 1];
    const int xL = bb * STARTI + opL;
    const int xR = bb * STARTI + opR;

    const float4* pL = (const float4*)(g_p + (size_t)xL * PPW);                 // left cols
    const float4* pR = (const float4*)(g_p + (size_t)xR * PPW + GATES * HDIM);  // right cols
    const float4* cL = (const float4*)(chart + (size_t)(bb * CHART_LEN + opL) * KDIM);
    const float4* cR = (const float4*)(chart + (size_t)(bb * CHART_LEN + opR) * KDIM);
    const float4* b4 = (const float4*)bias;
    float4* oc = (float4*)(g_c + r * HDIM);
    float4* oh = (float4*)(g_h + r * HDIM);

    const int j4 = threadIdx.x;             // 256 threads x 4 floats = 1024 cols
    const int q = HDIM / 4;                 // float4 stride per gate

    float4 vi  = pL[0 * q + j4], vfl = pL[1 * q + j4], vfr = pL[2 * q + j4];
    float4 vo  = pL[3 * q + j4], vu  = pL[4 * q + j4];
    float4 wi  = pR[0 * q + j4], wfl = pR[1 * q + j4], wfr = pR[2 * q + j4];
    float4 wo  = pR[3 * q + j4], wu  = pR[4 * q + j4];
    float4 bi  = b4[0 * q + j4], bfl = b4[1 * q + j4], bfr = b4[2 * q + j4];
    float4 bo  = b4[3 * q + j4], bu  = b4[4 * q + j4];
    float4 ccl = cL[j4], ccr = cR[j4];

    float4 rc, rh;
    {
        float pi[4]  = {vi.x + wi.x + bi.x,   vi.y + wi.y + bi.y,   vi.z + wi.z + bi.z,   vi.w + wi.w + bi.w};
        float pf[4]  = {vfl.x + wfl.x + bfl.x, vfl.y + wfl.y + bfl.y, vfl.z + wfl.z + bfl.z, vfl.w + wfl.w + bfl.w};
        float pg[4]  = {vfr.x + wfr.x + bfr.x, vfr.y + wfr.y + bfr.y, vfr.z + wfr.z + bfr.z, vfr.w + wfr.w + bfr.w};
        float po[4]  = {vo.x + wo.x + bo.x,   vo.y + wo.y + bo.y,   vo.z + wo.z + bo.z,   vo.w + wo.w + bo.w};
        float pu[4]  = {vu.x + wu.x + bu.x,   vu.y + wu.y + bu.y,   vu.z + wu.z + bu.z,   vu.w + wu.w + bu.w};
        float l[4]   = {ccl.x, ccl.y, ccl.z, ccl.w};
        float rr[4]  = {ccr.x, ccr.y, ccr.z, ccr.w};
        float c[4], h[4];
#pragma unroll
        for (int e = 0; e < 4; e++) {
            float ig = sigmoidf_(pi[e]);
            float fl = sigmoidf_(pf[e]);
            float fr = sigmoidf_(pg[e]);
            float og = sigmoidf_(po[e]);
            float ut = tanhf(pu[e]);
            c[e] = fl * l[e] + fr * rr[e] + ig * ut;
            h[e] = og * tanhf(c[e]);
        }
        rc = make_float4(c[0], c[1], c[2], c[3]);
        rh = make_float4(h[0], h[1], h[2], h[3]);
    }
    oc[j4] = rc;
    oh[j4] = rh;
}

// ---------------------------------------------------------------------------
// K4: per (step,batch): energy, softmax over amb, combine, write out row
// ---------------------------------------------------------------------------
__global__ __launch_bounds__(256) void combine_kernel(const float* __restrict__ eu,
                                                      float* __restrict__ out)
{
    __shared__ float s_eu[HDIM];
    __shared__ float s_e[AMB];
    __shared__ float s_w[AMB];
    __shared__ float s_red[8];
    __shared__ float s_unorm;

    const int tid = threadIdx.x;
    const int sb = blockIdx.x;
    const int step = sb >> 5;
    const int bb = sb & 31;
    const size_t base = (size_t)sb * AMB * HDIM;

    float part = 0.f;
#pragma unroll
    for (int t = 0; t < 4; t++) {
        int j = tid + t * 256;
        float v = eu[j];
        s_eu[j] = v;
        part += v * v;
    }
#pragma unroll
    for (int off = 16; off; off >>= 1) part += __shfl_xor_sync(0xffffffffu, part, off);
    if ((tid & 31) == 0) s_red[tid >> 5] = part;
    __syncthreads();
    if (tid == 0) {
        float s = 0.f;
#pragma unroll
        for (int w = 0; w < 8; w++) s += s_red[w];
        s_unorm = fmaxf(sqrtf(s), 1e-8f);
    }
    __syncthreads();

    const int warp = tid >> 5, lane = tid & 31;
#pragma unroll
    for (int t = 0; t < 4; t++) {
        int a = warp * 4 + t;
        const float* hrow = g_h + base + (size_t)a * HDIM;
        float s2 = 0.f, se = 0.f;
        for (int j = lane; j < HDIM; j += 32) {
            float hv = hrow[j];
            s2 += hv * hv;
            se += hv * s_eu[j];
        }
#pragma unroll
        for (int off = 16; off; off >>= 1) {
            s2 += __shfl_xor_sync(0xffffffffu, s2, off);
            se += __shfl_xor_sync(0xffffffffu, se, off);
        }
        if (lane == 0) {
            float hn = fmaxf(sqrtf(s2), 1e-8f);
            s_e[a] = se / (s_unorm * hn);
        }
    }
    __syncthreads();

    if (tid < 32) {
        float x = s_e[tid];
        float m = x;
#pragma unroll
        for (int off = 16; off; off >>= 1) m = fmaxf(m, __shfl_xor_sync(0xffffffffu, m, off));
        float p = __expf(x - m);
        float s = p;
#pragma unroll
        for (int off = 16; off; off >>= 1) s += __shfl_xor_sync(0xffffffffu, s, off);
        s_w[tid] = p / s;
    }
    __syncthreads();

    float* orow = out + ((size_t)bb * CHART_LEN + (STARTI + step)) * KDIM;
#pragma unroll
    for (int t = 0; t < 4; t++) {
        int j = tid + t * 256;
        float accC = 0.f, accH = 0.f;
#pragma unroll 8
        for (int a = 0; a < AMB; a++) {
            float w = s_w[a];
            accC += w * g_c[base + (size_t)a * HDIM + j];
            accH += w * g_h[base + (size_t)a * HDIM + j];
        }
        orow[j] = accC;
        orow[HDIM + j] = accH;
    }
}

// ---------------------------------------------------------------------------
extern "C" void kernel_launch(void* const* d_in, const int* in_sizes, int n_in,
                              void* d_out, int out_size) {
    const float* chart = (const float*)d_in[0];
    const int*   ops   = (const int*)d_in[1];
    const float* U     = (const float*)d_in[3];
    const float* bias  = (const float*)d_in[4];
    const float* eu    = (const float*)d_in[5];
    float* out = (float*)d_out;

    const int n4 = BSZ * STARTI * KDIM / 4;
    copy_kernel<<<n4 / 256, 256>>>((const float4*)chart, (float4*)out);

    // K2: one GEMM over 8192 distinct h-vectors (16x less FLOPs than naive)
    dim3 g2(HDIM / BN, NX / BM, 2);             // (32, 128, 2)
    pp_gemm_kernel<<<g2, 256>>>(chart, U);

    // K3: gather-add preacts + LSTM gates for all 131072 rows
    gates_kernel<<<NROWS, 256>>>(chart, ops, bias);

    // K4: softmax + combine + write rows [256,384)
    combine_kernel<<<STEPS * BSZ, 256>>>(eu, out);
}

// round 4
// speedup vs baseline: 30.1802x; 2.4328x over previous
#include <cuda_runtime.h>
#include <cuda_bf16.h>
#include <math.h>
#include <cstdint>

// Problem constants
#define HDIM 1024
#define KDIM 2048
#define GATES 5
#define BSZ 32
#define STEPS 128
#define AMB 32
#define STARTI 256
#define CHART_LEN 384
#define NROWS (STEPS * BSZ * AMB)   // 131072
#define NX (BSZ * STARTI)           // 8192 distinct h-vectors
#define PPW (2 * GATES * HDIM)      // 10240 PP cols

// Static device scratch
__device__ float g_p[(size_t)NX * PPW];
__device__ float g_c[(size_t)NROWS * HDIM];
__device__ float g_h[(size_t)NROWS * HDIM];
__device__ __nv_bfloat16 g_a0[(size_t)NX * HDIM];
__device__ __nv_bfloat16 g_a1[(size_t)NX * HDIM];
__device__ __nv_bfloat16 g_u0[(size_t)PPW * HDIM];
__device__ __nv_bfloat16 g_u1[(size_t)PPW * HDIM];

__device__ __forceinline__ float sigmoidf_(float x) {
    return 1.0f / (1.0f + __expf(-x));
}

__device__ __forceinline__ uint32_t smem_u32(const void* p) {
    uint32_t a;
    asm("{ .reg .u64 t; cvta.to.shared.u64 t, %1; cvt.u32.u64 %0, t; }" : "=r"(a) : "l"(p));
    return a;
}

#define LDMATRIX_X4(r, addr) \
    asm volatile("ldmatrix.sync.aligned.m8n8.x4.shared.b16 {%0,%1,%2,%3}, [%4];" \
        : "=r"((r)[0]), "=r"((r)[1]), "=r"((r)[2]), "=r"((r)[3]) : "r"(addr))

__device__ __forceinline__ void mma16816(float* d, const uint32_t* a, const uint32_t* b) {
    asm volatile(
        "mma.sync.aligned.m16n8k16.row.col.f32.bf16.bf16.f32 "
        "{%0,%1,%2,%3}, {%4,%5,%6,%7}, {%8,%9}, {%0,%1,%2,%3};"
        : "+f"(d[0]), "+f"(d[1]), "+f"(d[2]), "+f"(d[3])
        : "r"(a[0]), "r"(a[1]), "r"(a[2]), "r"(a[3]), "r"(b[0]), "r"(b[1]));
}

// ---------------------------------------------------------------------------
// K1: copy chart rows [0,256)
// ---------------------------------------------------------------------------
__global__ __launch_bounds__(256) void copy_kernel(const float4* __restrict__ src,
                                                   float4* __restrict__ dst) {
    int i4 = blockIdx.x * 256 + threadIdx.x;
    const int per_batch = STARTI * KDIM / 4;
    const int full_batch = CHART_LEN * KDIM / 4;
    int b = i4 / per_batch;
    int rem = i4 - b * per_batch;
    size_t s = (size_t)b * full_batch + rem;
    dst[s] = src[s];
}

// ---------------------------------------------------------------------------
// bf16 hi/lo split precompute for A (chart h-halves) and U (reindexed)
// ---------------------------------------------------------------------------
__device__ __forceinline__ void split_store(__nv_bfloat16* hi_arr, __nv_bfloat16* lo_arr,
                                            size_t off, float4 v) {
    float vv[4] = {v.x, v.y, v.z, v.w};
    __nv_bfloat16 h[4], l[4];
#pragma unroll
    for (int e = 0; e < 4; e++) {
        h[e] = __float2bfloat16(vv[e]);
        l[e] = __float2bfloat16(vv[e] - __bfloat162float(h[e]));
    }
    __nv_bfloat162 h01 = {h[0], h[1]}, h23 = {h[2], h[3]};
    __nv_bfloat162 l01 = {l[0], l[1]}, l23 = {l[2], l[3]};
    uint2 uh, ul;
    uh.x = *reinterpret_cast<uint32_t*>(&h01); uh.y = *reinterpret_cast<uint32_t*>(&h23);
    ul.x = *reinterpret_cast<uint32_t*>(&l01); ul.y = *reinterpret_cast<uint32_t*>(&l23);
    *reinterpret_cast<uint2*>(hi_arr + off) = uh;
    *reinterpret_cast<uint2*>(lo_arr + off) = ul;
}

__global__ __launch_bounds__(256) void splitA_kernel(const float* __restrict__ chart) {
    size_t i = (size_t)blockIdx.x * 256 + threadIdx.x;
    int x = (int)(i >> 8);
    int k = ((int)i & 255) * 4;
    int bb = x >> 8, op = x & 255;
    float4 v = *(const float4*)(chart + ((size_t)(bb * CHART_LEN + op)) * KDIM + HDIM + k);
    split_store(g_a0, g_a1, (size_t)x * HDIM + k, v);
}

__global__ __launch_bounds__(256) void splitU_kernel(const float* __restrict__ U) {
    size_t i = (size_t)blockIdx.x * 256 + threadIdx.x;
    int c = (int)(i >> 8);
    int k = ((int)i & 255) * 4;
    int side = c / (GATES * HDIM);
    int gj = c - side * (GATES * HDIM);
    float4 v = *(const float4*)(U + (size_t)gj * KDIM + side * HDIM + k);
    split_store(g_u0, g_u1, (size_t)c * HDIM + k, v);
}

// ---------------------------------------------------------------------------
// K2: HMMA warp-mma GEMM. PP[x, c] = sum_k A[x,k]*Ubf[c,k], 2-split (3 passes,
// fp32 accum). CTA tile 128x128, BK=32, 8 warps of 64x32 each.
// smem: 80B-padded rows (stride 40 halves) -> conflict-free ldmatrix.
// ---------------------------------------------------------------------------
#define LDS_STRIDE 40   // halves per row (32 data + 8 pad)

__global__ __launch_bounds__(256) void mma_gemm_kernel() {
    __shared__ __align__(16) __nv_bfloat16 sA0[128 * LDS_STRIDE];
    __shared__ __align__(16) __nv_bfloat16 sA1[128 * LDS_STRIDE];
    __shared__ __align__(16) __nv_bfloat16 sB0[128 * LDS_STRIDE];
    __shared__ __align__(16) __nv_bfloat16 sB1[128 * LDS_STRIDE];

    const int tid = threadIdx.x;
    const int wid = tid >> 5, lane = tid & 31;
    const int wm = wid >> 2;        // 0..1 -> M offset wm*64
    const int wn = wid & 3;         // 0..3 -> N offset wn*32
    const int nbase = blockIdx.x * 128;
    const int xbase = blockIdx.y * 128;

    const uint32_t uA0 = smem_u32(sA0), uA1 = smem_u32(sA1);
    const uint32_t uB0 = smem_u32(sB0), uB1 = smem_u32(sB1);

    // ldmatrix lane-address components (bytes)
    const int aRow = (lane & 15);            // + row0
    const int aCol = (lane >> 4) << 4;       // + k_bytes
    const int bRow = ((lane >> 4) << 3) + (lane & 7);
    const int bCol = ((lane >> 3) & 1) << 4;

    float acc[4][4][4];
#pragma unroll
    for (int mi = 0; mi < 4; mi++)
#pragma unroll
        for (int ni = 0; ni < 4; ni++)
#pragma unroll
            for (int e = 0; e < 4; e++) acc[mi][ni][e] = 0.f;

    // thread->load mapping (2048 uint4 per chunk: 4 tiles x 128 rows x 4 uint4)
    for (int kc = 0; kc < HDIM / 32; kc++) {
        const int kb = kc * 32;
#pragma unroll
        for (int it = 0; it < 8; it++) {
            int id = tid + it * 256;
            int t = id >> 9;
            int rem = id & 511;
            int row = rem >> 2, q = rem & 3;
            const __nv_bfloat16* src;
            __nv_bfloat16* dst;
            if (t == 0)      { src = g_a0 + (size_t)(xbase + row) * HDIM + kb + q * 8; dst = sA0; }
            else if (t == 1) { src = g_a1 + (size_t)(xbase + row) * HDIM + kb + q * 8; dst = sA1; }
            else if (t == 2) { src = g_u0 + (size_t)(nbase + row) * HDIM + kb + q * 8; dst = sB0; }
            else             { src = g_u1 + (size_t)(nbase + row) * HDIM + kb + q * 8; dst = sB1; }
            *(uint4*)(dst + row * LDS_STRIDE + q * 8) = *(const uint4*)src;
        }
        __syncthreads();

#pragma unroll
        for (int ks = 0; ks < 2; ks++) {
            const int kbytes = ks * 32;
            // B fragments: 2 x ldmatrix.x4 per split (each covers 2 n8-tiles)
            uint32_t b0f[2][4], b1f[2][4];
#pragma unroll
            for (int nt = 0; nt < 2; nt++) {
                uint32_t off = (uint32_t)((wn * 32 + nt * 16 + bRow) * (LDS_STRIDE * 2)
                                          + kbytes + bCol);
                LDMATRIX_X4(b0f[nt], uB0 + off);
                LDMATRIX_X4(b1f[nt], uB1 + off);
            }
#pragma unroll
            for (int mi = 0; mi < 4; mi++) {
                uint32_t a0f[4], a1f[4];
                uint32_t off = (uint32_t)((wm * 64 + mi * 16 + aRow) * (LDS_STRIDE * 2)
                                          + kbytes + aCol);
                LDMATRIX_X4(a0f, uA0 + off);
                LDMATRIX_X4(a1f, uA1 + off);
#pragma unroll
                for (int ni = 0; ni < 4; ni++) {
                    const uint32_t* pb0 = &b0f[ni >> 1][(ni & 1) * 2];
                    const uint32_t* pb1 = &b1f[ni >> 1][(ni & 1) * 2];
                    mma16816(acc[mi][ni], a0f, pb0);
                    mma16816(acc[mi][ni], a0f, pb1);
                    mma16816(acc[mi][ni], a1f, pb0);
                }
            }
        }
        __syncthreads();
    }

    // epilogue: c-frag: d0,d1 -> (row grp, col 2c..2c+1); d2,d3 -> row+8
    const int cr = lane >> 2;
    const int cc = (lane & 3) * 2;
#pragma unroll
    for (int mi = 0; mi < 4; mi++) {
        int row0 = xbase + wm * 64 + mi * 16 + cr;
#pragma unroll
        for (int ni = 0; ni < 4; ni++) {
            int col = nbase + wn * 32 + ni * 8 + cc;
            float* p0 = g_p + (size_t)row0 * PPW + col;
            float* p1 = g_p + (size_t)(row0 + 8) * PPW + col;
            *(float2*)p0 = make_float2(acc[mi][ni][0], acc[mi][ni][1]);
            *(float2*)p1 = make_float2(acc[mi][ni][2], acc[mi][ni][3]);
        }
    }
}

// ---------------------------------------------------------------------------
// K3: gather-add preacts + gates. Blocks ordered (b, step, a) for PP L2 locality.
// ---------------------------------------------------------------------------
__global__ __launch_bounds__(256) void gates_kernel(
    const float* __restrict__ chart, const int* __restrict__ ops,
    const float* __restrict__ bias)
{
    const int bid = blockIdx.x;
    const int bb = bid >> 12;
    const int rem = bid & 4095;
    const size_t r = (size_t)(rem >> 5) * (BSZ * AMB) + bb * AMB + (rem & 31);

    const int opL = ops[2 * r];
    const int opR = ops[2 * r + 1];
    const int xL = bb * STARTI + opL;
    const int xR = bb * STARTI + opR;

    const float4* pL = (const float4*)(g_p + (size_t)xL * PPW);
    const float4* pR = (const float4*)(g_p + (size_t)xR * PPW + GATES * HDIM);
    const float4* cL = (const float4*)(chart + (size_t)(bb * CHART_LEN + opL) * KDIM);
    const float4* cR = (const float4*)(chart + (size_t)(bb * CHART_LEN + opR) * KDIM);
    const float4* b4 = (const float4*)bias;
    float4* oc = (float4*)(g_c + r * HDIM);
    float4* oh = (float4*)(g_h + r * HDIM);

    const int j4 = threadIdx.x;
    const int q = HDIM / 4;

    float4 vi = pL[0 * q + j4], vfl = pL[1 * q + j4], vfr = pL[2 * q + j4];
    float4 vo = pL[3 * q + j4], vu = pL[4 * q + j4];
    float4 wi = pR[0 * q + j4], wfl = pR[1 * q + j4], wfr = pR[2 * q + j4];
    float4 wo = pR[3 * q + j4], wu = pR[4 * q + j4];
    float4 bi = b4[0 * q + j4], bfl = b4[1 * q + j4], bfr = b4[2 * q + j4];
    float4 bo = b4[3 * q + j4], bu = b4[4 * q + j4];
    float4 ccl = cL[j4], ccr = cR[j4];

    float pi[4] = {vi.x + wi.x + bi.x, vi.y + wi.y + bi.y, vi.z + wi.z + bi.z, vi.w + wi.w + bi.w};
    float pf[4] = {vfl.x + wfl.x + bfl.x, vfl.y + wfl.y + bfl.y, vfl.z + wfl.z + bfl.z, vfl.w + wfl.w + bfl.w};
    float pg[4] = {vfr.x + wfr.x + bfr.x, vfr.y + wfr.y + bfr.y, vfr.z + wfr.z + bfr.z, vfr.w + wfr.w + bfr.w};
    float po[4] = {vo.x + wo.x + bo.x, vo.y + wo.y + bo.y, vo.z + wo.z + bo.z, vo.w + wo.w + bo.w};
    float pu[4] = {vu.x + wu.x + bu.x, vu.y + wu.y + bu.y, vu.z + wu.z + bu.z, vu.w + wu.w + bu.w};
    float l[4] = {ccl.x, ccl.y, ccl.z, ccl.w};
    float rr[4] = {ccr.x, ccr.y, ccr.z, ccr.w};
    float c[4], h[4];
#pragma unroll
    for (int e = 0; e < 4; e++) {
        float ig = sigmoidf_(pi[e]);
        float fl = sigmoidf_(pf[e]);
        float fr = sigmoidf_(pg[e]);
        float og = sigmoidf_(po[e]);
        float ut = tanhf(pu[e]);
        c[e] = fl * l[e] + fr * rr[e] + ig * ut;
        h[e] = og * tanhf(c[e]);
    }
    oc[j4] = make_float4(c[0], c[1], c[2], c[3]);
    oh[j4] = make_float4(h[0], h[1], h[2], h[3]);
}

// ---------------------------------------------------------------------------
// K4: per (step,batch) softmax-combine, write out rows [256,384)
// ---------------------------------------------------------------------------
__global__ __launch_bounds__(256) void combine_kernel(const float* __restrict__ eu,
                                                      float* __restrict__ out)
{
    __shared__ float s_eu[HDIM];
    __shared__ float s_e[AMB];
    __shared__ float s_w[AMB];
    __shared__ float s_red[8];
    __shared__ float s_unorm;

    const int tid = threadIdx.x;
    const int sb = blockIdx.x;
    const int step = sb >> 5;
    const int bb = sb & 31;
    const size_t base = (size_t)sb * AMB * HDIM;

    float part = 0.f;
#pragma unroll
    for (int t = 0; t < 4; t++) {
        int j = tid + t * 256;
        float v = eu[j];
        s_eu[j] = v;
        part += v * v;
    }
#pragma unroll
    for (int off = 16; off; off >>= 1) part += __shfl_xor_sync(0xffffffffu, part, off);
    if ((tid & 31) == 0) s_red[tid >> 5] = part;
    __syncthreads();
    if (tid == 0) {
        float s = 0.f;
#pragma unroll
        for (int w = 0; w < 8; w++) s += s_red[w];
        s_unorm = fmaxf(sqrtf(s), 1e-8f);
    }
    __syncthreads();

    const int warp = tid >> 5, lane = tid & 31;
#pragma unroll
    for (int t = 0; t < 4; t++) {
        int a = warp * 4 + t;
        const float* hrow = g_h + base + (size_t)a * HDIM;
        float s2 = 0.f, se = 0.f;
        for (int j = lane; j < HDIM; j += 32) {
            float hv = hrow[j];
            s2 += hv * hv;
            se += hv * s_eu[j];
        }
#pragma unroll
        for (int off = 16; off; off >>= 1) {
            s2 += __shfl_xor_sync(0xffffffffu, s2, off);
            se += __shfl_xor_sync(0xffffffffu, se, off);
        }
        if (lane == 0) {
            float hn = fmaxf(sqrtf(s2), 1e-8f);
            s_e[a] = se / (s_unorm * hn);
        }
    }
    __syncthreads();

    if (tid < 32) {
        float x = s_e[tid];
        float m = x;
#pragma unroll
        for (int off = 16; off; off >>= 1) m = fmaxf(m, __shfl_xor_sync(0xffffffffu, m, off));
        float p = __expf(x - m);
        float s = p;
#pragma unroll
        for (int off = 16; off; off >>= 1) s += __shfl_xor_sync(0xffffffffu, s, off);
        s_w[tid] = p / s;
    }
    __syncthreads();

    float* orow = out + ((size_t)bb * CHART_LEN + (STARTI + step)) * KDIM;
#pragma unroll
    for (int t = 0; t < 4; t++) {
        int j = tid + t * 256;
        float accC = 0.f, accH = 0.f;
#pragma unroll 8
        for (int a = 0; a < AMB; a++) {
            float w = s_w[a];
            accC += w * g_c[base + (size_t)a * HDIM + j];
            accH += w * g_h[base + (size_t)a * HDIM + j];
        }
        orow[j] = accC;
        orow[HDIM + j] = accH;
    }
}

// ---------------------------------------------------------------------------
extern "C" void kernel_launch(void* const* d_in, const int* in_sizes, int n_in,
                              void* d_out, int out_size) {
    const float* chart = (const float*)d_in[0];
    const int*   ops   = (const int*)d_in[1];
    const float* U     = (const float*)d_in[3];
    const float* bias  = (const float*)d_in[4];
    const float* eu    = (const float*)d_in[5];
    float* out = (float*)d_out;

    const int n4 = BSZ * STARTI * KDIM / 4;
    copy_kernel<<<n4 / 256, 256>>>((const float4*)chart, (float4*)out);

    splitA_kernel<<<NX, 256>>>(chart);
    splitU_kernel<<<PPW, 256>>>(U);

    dim3 g2(PPW / 128, NX / 128);   // (80, 64)
    mma_gemm_kernel<<<g2, 256>>>();

    gates_kernel<<<NROWS, 256>>>(chart, ops, bias);

    combine_kernel<<<STEPS * BSZ, 256>>>(eu, out);
}